// round 4
// baseline (speedup 1.0000x reference)
#include <cuda_runtime.h>
#include <cuda_bf16.h>

// PreprocessLayerTorch: MIC pairwise distances + shifts + element one-hot.
// Output layout (float32), flattened:
//   [0, n*4)                      onehot (n, 4)
//   [n*4, n*4 + n*n)              dist_masked (n, n)
//   [n*4 + n*n, +3nn)             shift (n, n, 3)

#define NMAX 8192
__device__ float g_fx[NMAX];
__device__ float g_fy[NMAX];
__device__ float g_fz[NMAX];

// Fused: fractional coords (wrapped) + onehot (one float4 store per atom).
__global__ void frac_onehot_kernel(const float* __restrict__ coord,
                                   const float* __restrict__ cell,
                                   const int* __restrict__ elems,
                                   float* __restrict__ onehot_out, int n) {
    int i = blockIdx.x * blockDim.x + threadIdx.x;
    if (i >= n) return;

    float c00 = cell[0], c01 = cell[1], c02 = cell[2];
    float c10 = cell[3], c11 = cell[4], c12 = cell[5];
    float c20 = cell[6], c21 = cell[7], c22 = cell[8];

    float det = c00 * (c11 * c22 - c12 * c21)
              - c01 * (c10 * c22 - c12 * c20)
              + c02 * (c10 * c21 - c11 * c20);
    float id = 1.0f / det;

    float i00 =  (c11 * c22 - c12 * c21) * id;
    float i01 = -(c01 * c22 - c02 * c21) * id;
    float i02 =  (c01 * c12 - c02 * c11) * id;
    float i10 = -(c10 * c22 - c12 * c20) * id;
    float i11 =  (c00 * c22 - c02 * c20) * id;
    float i12 = -(c00 * c12 - c02 * c10) * id;
    float i20 =  (c10 * c21 - c11 * c20) * id;
    float i21 = -(c00 * c21 - c01 * c20) * id;
    float i22 =  (c00 * c11 - c01 * c10) * id;

    float x = coord[3 * i + 0];
    float y = coord[3 * i + 1];
    float z = coord[3 * i + 2];

    float fx = x * i00 + y * i10 + z * i20;
    float fy = x * i01 + y * i11 + z * i21;
    float fz = x * i02 + y * i12 + z * i22;

    fx -= floorf(fx);
    fy -= floorf(fy);
    fz -= floorf(fz);

    g_fx[i] = fx;
    g_fy[i] = fy;
    g_fz[i] = fz;

    int e = elems[i];
    *reinterpret_cast<float4*>(onehot_out + 4 * i) =
        make_float4(e == 1 ? 1.0f : 0.0f, e == 6 ? 1.0f : 0.0f,
                    e == 7 ? 1.0f : 0.0f, e == 8 ? 1.0f : 0.0f);
}

// One block handles JPB consecutive j's of one row i. No shared memory:
//  - dist: thread t stores float4 for j = base+4t..+3 (warp-contiguous).
//  - shift: thread t stores 3 float4s; each covers exactly 2 consecutive j's
//    whose shifts it recomputes directly (3 subs + 3 rints each) from the
//    L1-resident fractional arrays. Every STG.128 is warp-contiguous.
#define JPB 1024          // j's per block
#define TPB 256           // threads per block

__global__ __launch_bounds__(TPB)
void pair_kernel(const float* __restrict__ cell,
                 float* __restrict__ dist_out,
                 float* __restrict__ shift_out, int n) {
    int i = blockIdx.y;
    int base_j = blockIdx.x * JPB;
    int t = threadIdx.x;

    float fxi = g_fx[i], fyi = g_fy[i], fzi = g_fz[i];

    // ---------- dist phase ----------
    {
        int j0 = base_j + t * 4;
        if (j0 < n) {
            float c00 = __ldg(cell + 0), c01 = __ldg(cell + 1), c02 = __ldg(cell + 2);
            float c10 = __ldg(cell + 3), c11 = __ldg(cell + 4), c12 = __ldg(cell + 5);
            float c20 = __ldg(cell + 6), c21 = __ldg(cell + 7), c22 = __ldg(cell + 8);

            float4 fxj = *reinterpret_cast<const float4*>(g_fx + j0);
            float4 fyj = *reinterpret_cast<const float4*>(g_fy + j0);
            float4 fzj = *reinterpret_cast<const float4*>(g_fz + j0);

            float fxs[4] = {fxj.x, fxj.y, fxj.z, fxj.w};
            float fys[4] = {fyj.x, fyj.y, fyj.z, fyj.w};
            float fzs[4] = {fzj.x, fzj.y, fzj.z, fzj.w};

            float dvals[4];
#pragma unroll
            for (int k = 0; k < 4; k++) {
                float dfx = fxs[k] - fxi;
                float dfy = fys[k] - fyi;
                float dfz = fzs[k] - fzi;
                dfx -= rintf(dfx);
                dfy -= rintf(dfy);
                dfz -= rintf(dfz);

                float dx = dfx * c00 + dfy * c10 + dfz * c20;
                float dy = dfx * c01 + dfy * c11 + dfz * c21;
                float dz = dfx * c02 + dfy * c12 + dfz * c22;

                float d2 = dx * dx + dy * dy + dz * dz;
                bool m = (d2 > 0.0f) && (d2 < 25.0f);  // RC = 5.0
                dvals[k] = m ? sqrtf(d2) : 0.0f;
            }

            long long dbase = (long long)i * n + j0;
            *reinterpret_cast<float4*>(dist_out + dbase) =
                make_float4(dvals[0], dvals[1], dvals[2], dvals[3]);
        }
    }

    // ---------- shift phase ----------
    {
        int jcount = n - base_j;
        if (jcount > JPB) jcount = JPB;
        int nfloat = jcount * 3;             // 3*jcount, divisible by 4 (jcount%4==0)
        long long sbase = ((long long)i * n + base_j) * 3;

#pragma unroll
        for (int s = 0; s < 3; s++) {
            int f = s * TPB + t;             // float4 index within block region
            int g = 4 * f;                   // starting float (component) index
            if (g + 3 < nfloat) {
                int jA = g / 3;              // local j of first component
                int cA = g - 3 * jA;         // component offset 0..2
                int ja = base_j + jA;

                // recompute shift for jA and jA+1 (both always needed & valid)
                float a0 = -rintf(g_fx[ja]     - fxi);
                float a1 = -rintf(g_fy[ja]     - fyi);
                float a2 = -rintf(g_fz[ja]     - fzi);
                float b0 = -rintf(g_fx[ja + 1] - fxi);
                float b1 = -rintf(g_fy[ja + 1] - fyi);
                float b2 = -rintf(g_fz[ja + 1] - fzi);

                float arr[6] = {a0, a1, a2, b0, b1, b2};
                *reinterpret_cast<float4*>(shift_out + sbase + g) =
                    make_float4(arr[cA], arr[cA + 1], arr[cA + 2], arr[cA + 3]);
            } else if (g < nfloat) {
                // generic scalar fallback (unused when jcount % 4 == 0)
                for (int c = 0; c < 4 && g + c < nfloat; c++) {
                    int gf = g + c;
                    int jj = base_j + gf / 3;
                    int cc = gf % 3;
                    float fj = (cc == 0) ? g_fx[jj] : (cc == 1) ? g_fy[jj] : g_fz[jj];
                    float fi = (cc == 0) ? fxi : (cc == 1) ? fyi : fzi;
                    shift_out[sbase + gf] = -rintf(fj - fi);
                }
            }
        }
    }
}

extern "C" void kernel_launch(void* const* d_in, const int* in_sizes, int n_in,
                              void* d_out, int out_size) {
    const float* coord = (const float*)d_in[0];   // (n, 3) float32
    const float* cell  = (const float*)d_in[1];   // (3, 3) float32
    const int*   elems = (const int*)d_in[2];     // (n,)   int32

    int n = in_sizes[0] / 3;

    float* out       = (float*)d_out;
    float* dist_out  = out + (long long)n * 4;      // n*n
    float* shift_out = dist_out + (long long)n * n; // n*n*3

    // 1) fused fractional coords + onehot
    {
        int threads = 256;
        int blocks = (n + threads - 1) / threads;
        frac_onehot_kernel<<<blocks, threads>>>(coord, cell, elems, out, n);
    }

    // 2) pairwise dist + shift
    {
        int jblocks = (n + JPB - 1) / JPB;
        dim3 grid(jblocks, n);
        pair_kernel<<<grid, TPB>>>(cell, dist_out, shift_out, n);
    }
}

// round 5
// speedup vs baseline: 1.8073x; 1.8073x over previous
#include <cuda_runtime.h>
#include <cuda_bf16.h>

// PreprocessLayerTorch: MIC pairwise distances + shifts + element one-hot.
// Output layout (float32), flattened:
//   [0, n*4)                      onehot (n, 4)
//   [n*4, n*4 + n*n)              dist_masked (n, n)
//   [n*4 + n*n, +3nn)             shift (n, n, 3)

#define NMAX 8192
__device__ float g_fx[NMAX];
__device__ float g_fy[NMAX];
__device__ float g_fz[NMAX];

// Fused: fractional coords (wrapped) + onehot (one float4 store per atom).
__global__ void frac_onehot_kernel(const float* __restrict__ coord,
                                   const float* __restrict__ cell,
                                   const int* __restrict__ elems,
                                   float* __restrict__ onehot_out, int n) {
    int i = blockIdx.x * blockDim.x + threadIdx.x;
    if (i >= n) return;

    float c00 = cell[0], c01 = cell[1], c02 = cell[2];
    float c10 = cell[3], c11 = cell[4], c12 = cell[5];
    float c20 = cell[6], c21 = cell[7], c22 = cell[8];

    float det = c00 * (c11 * c22 - c12 * c21)
              - c01 * (c10 * c22 - c12 * c20)
              + c02 * (c10 * c21 - c11 * c20);
    float id = 1.0f / det;

    float i00 =  (c11 * c22 - c12 * c21) * id;
    float i01 = -(c01 * c22 - c02 * c21) * id;
    float i02 =  (c01 * c12 - c02 * c11) * id;
    float i10 = -(c10 * c22 - c12 * c20) * id;
    float i11 =  (c00 * c22 - c02 * c20) * id;
    float i12 = -(c00 * c12 - c02 * c10) * id;
    float i20 =  (c10 * c21 - c11 * c20) * id;
    float i21 = -(c00 * c21 - c01 * c20) * id;
    float i22 =  (c00 * c11 - c01 * c10) * id;

    float x = coord[3 * i + 0];
    float y = coord[3 * i + 1];
    float z = coord[3 * i + 2];

    float fx = x * i00 + y * i10 + z * i20;
    float fy = x * i01 + y * i11 + z * i21;
    float fz = x * i02 + y * i12 + z * i22;

    fx -= floorf(fx);
    fy -= floorf(fy);
    fz -= floorf(fz);

    g_fx[i] = fx;
    g_fy[i] = fy;
    g_fz[i] = fz;

    int e = elems[i];
    *reinterpret_cast<float4*>(onehot_out + 4 * i) =
        make_float4(e == 1 ? 1.0f : 0.0f, e == 6 ? 1.0f : 0.0f,
                    e == 7 ? 1.0f : 0.0f, e == 8 ? 1.0f : 0.0f);
}

// Block = (JPB j's) x (ROWS i's). j-frac coords loaded to registers ONCE and
// reused across ROWS rows (cuts LSU instruction count ~17%).
// Shift staging is warp-local (each warp owns 128 j's): only __syncwarp needed.
// All global stores are warp-contiguous STG.128.
#define JPB  1024
#define TPB  256
#define ROWS 4

__global__ __launch_bounds__(TPB)
void pair_kernel(const float* __restrict__ cell,
                 float* __restrict__ dist_out,
                 float* __restrict__ shift_out, int n) {
    __shared__ float s_shift[TPB / 32][384];   // 12 KB, per-warp 128 j's * 3

    int w = threadIdx.x >> 5;
    int l = threadIdx.x & 31;
    int base_j = blockIdx.x * JPB;
    int base_i = blockIdx.y * ROWS;
    int jw = base_j + w * 128;        // warp's j base
    int j0 = jw + l * 4;              // thread's first j
    bool act = (j0 < n);

    float c00 = __ldg(cell + 0), c01 = __ldg(cell + 1), c02 = __ldg(cell + 2);
    float c10 = __ldg(cell + 3), c11 = __ldg(cell + 4), c12 = __ldg(cell + 5);
    float c20 = __ldg(cell + 6), c21 = __ldg(cell + 7), c22 = __ldg(cell + 8);

    // Load this thread's 4 j-atoms' fractional coords once.
    float fxs[4], fys[4], fzs[4];
    if (act) {
        float4 fxj = *reinterpret_cast<const float4*>(g_fx + j0);
        float4 fyj = *reinterpret_cast<const float4*>(g_fy + j0);
        float4 fzj = *reinterpret_cast<const float4*>(g_fz + j0);
        fxs[0] = fxj.x; fxs[1] = fxj.y; fxs[2] = fxj.z; fxs[3] = fxj.w;
        fys[0] = fyj.x; fys[1] = fyj.y; fys[2] = fyj.z; fys[3] = fyj.w;
        fzs[0] = fzj.x; fzs[1] = fzj.y; fzs[2] = fzj.z; fzs[3] = fzj.w;
    }

    // Valid j count in this warp's region (n % 4 == 0 -> nq float4s exact).
    int jcount_w = n - jw;
    if (jcount_w > 128) jcount_w = 128;
    if (jcount_w < 0) jcount_w = 0;
    int nq = (jcount_w * 3) >> 2;     // valid shift float4s in warp region

    for (int r = 0; r < ROWS; r++) {
        int i = base_i + r;
        if (i >= n) break;

        float fxi = g_fx[i], fyi = g_fy[i], fzi = g_fz[i];

        if (act) {
            float dvals[4];
            float svals[12];
#pragma unroll
            for (int k = 0; k < 4; k++) {
                float dfx = fxs[k] - fxi;
                float dfy = fys[k] - fyi;
                float dfz = fzs[k] - fzi;

                float sx = -rintf(dfx);
                float sy = -rintf(dfy);
                float sz = -rintf(dfz);
                dfx += sx;
                dfy += sy;
                dfz += sz;

                float dx = dfx * c00 + dfy * c10 + dfz * c20;
                float dy = dfx * c01 + dfy * c11 + dfz * c21;
                float dz = dfx * c02 + dfy * c12 + dfz * c22;

                float d2 = dx * dx + dy * dy + dz * dz;
                bool m = (d2 > 0.0f) && (d2 < 25.0f);  // RC = 5.0
                dvals[k] = m ? sqrtf(d2) : 0.0f;
                svals[3 * k + 0] = sx;
                svals[3 * k + 1] = sy;
                svals[3 * k + 2] = sz;
            }

            // dist: warp-contiguous float4 store
            long long dbase = (long long)i * n + j0;
            *reinterpret_cast<float4*>(dist_out + dbase) =
                make_float4(dvals[0], dvals[1], dvals[2], dvals[3]);

            // stage shift (natural layout, 12 floats per lane)
            float* sm = &s_shift[w][l * 12];
            reinterpret_cast<float4*>(sm)[0] =
                make_float4(svals[0], svals[1], svals[2], svals[3]);
            reinterpret_cast<float4*>(sm)[1] =
                make_float4(svals[4], svals[5], svals[6], svals[7]);
            reinterpret_cast<float4*>(sm)[2] =
                make_float4(svals[8], svals[9], svals[10], svals[11]);
        }
        __syncwarp();

        // warp-local coalesced writeback: instruction s writes float4 (s*32+l)
        if (nq > 0) {
            long long sbase = ((long long)i * n + jw) * 3;
            const float4* smv = reinterpret_cast<const float4*>(&s_shift[w][0]);
            float4* dst = reinterpret_cast<float4*>(shift_out + sbase);
#pragma unroll
            for (int s = 0; s < 3; s++) {
                int q = s * 32 + l;
                if (q < nq) dst[q] = smv[q];
            }
        }
        __syncwarp();   // protect smem before next row overwrites
    }
}

extern "C" void kernel_launch(void* const* d_in, const int* in_sizes, int n_in,
                              void* d_out, int out_size) {
    const float* coord = (const float*)d_in[0];   // (n, 3) float32
    const float* cell  = (const float*)d_in[1];   // (3, 3) float32
    const int*   elems = (const int*)d_in[2];     // (n,)   int32

    int n = in_sizes[0] / 3;

    float* out       = (float*)d_out;
    float* dist_out  = out + (long long)n * 4;      // n*n
    float* shift_out = dist_out + (long long)n * n; // n*n*3

    // 1) fused fractional coords + onehot
    {
        int threads = 256;
        int blocks = (n + threads - 1) / threads;
        frac_onehot_kernel<<<blocks, threads>>>(coord, cell, elems, out, n);
    }

    // 2) pairwise dist + shift (ROWS rows per block)
    {
        int jblocks = (n + JPB - 1) / JPB;
        int iblocks = (n + ROWS - 1) / ROWS;
        dim3 grid(jblocks, iblocks);
        pair_kernel<<<grid, TPB>>>(cell, dist_out, shift_out, n);
    }
}